// round 11
// baseline (speedup 1.0000x reference)
#include <cuda_runtime.h>
#include <cuda_fp16.h>
#include <cstdint>
#include <cstddef>

#define MTOT 2048
#define NTOT 4096
#define KTOT 4352
#define HDIM 1024
#define XDIM 2304

#define BM 128
#define BN 256
#define BK 64
#define NST 3
#define ROWB 144
#define A_BYTES (BM * ROWB)                     // 18432
#define B_BYTES (BN * ROWB)                     // 36864
#define STAGE_BYTES (A_BYTES + B_BYTES)         // 55296
#define BIAS_BYTE_OFF (NST * STAGE_BYTES)       // 165888
#define SMEM_BYTES (BIAS_BYTE_OFF + 1024)       // 166912
#define KTILES (KTOT / BK)                      // 68

__device__ __half g_Z[(size_t)MTOT * KTOT];
__device__ __half g_WB[(size_t)NTOT * KTOT];

__device__ __forceinline__ void cp16(void* sdst, const void* gsrc) {
    uint32_t s = (uint32_t)__cvta_generic_to_shared(sdst);
    asm volatile("cp.async.cg.shared.global [%0], [%1], 16;" :: "r"(s), "l"(gsrc));
}

__device__ __forceinline__ void ldsm4(uint32_t addr, uint32_t* r) {
    asm volatile("ldmatrix.sync.aligned.m8n8.x4.shared.b16 {%0,%1,%2,%3}, [%4];"
                 : "=r"(r[0]), "=r"(r[1]), "=r"(r[2]), "=r"(r[3]) : "r"(addr));
}

__device__ __forceinline__ float sigm(float v) { return 1.0f / (1.0f + __expf(-v)); }

// ---------------- merged convert kernel ----------------
__global__ __launch_bounds__(256) void conv_all(
    const float* __restrict__ x, const float* __restrict__ pt, const float* __restrict__ pl,
    const float* __restrict__ Wi, const float* __restrict__ Wf,
    const float* __restrict__ Wo, const float* __restrict__ Ws)
{
    int y = blockIdx.y;
    int c4 = blockIdx.x * 256 + threadIdx.x;
    if (c4 >= KTOT / 4) return;
    int col = c4 * 4;

    const float* src;
    __half* dst;
    if (y < MTOT) {
        int cc;
        if (col < XDIM)             { src = x  + (size_t)y * XDIM; cc = col; }
        else if (col < XDIM + HDIM) { src = pt + (size_t)y * HDIM; cc = col - XDIM; }
        else                        { src = pl + (size_t)y * HDIM; cc = col - XDIM - HDIM; }
        src += cc - col;
        dst = g_Z + (size_t)y * KTOT;
    } else {
        int g = y - MTOT;
        int n_tile = g >> 8, r = g & 255;
        int h = n_tile * 64 + (r >> 2);
        int gate = r & 3;
        const float* W = (gate == 0) ? Wi : (gate == 1) ? Wf : (gate == 2) ? Wo : Ws;
        src = W + (size_t)h * KTOT;
        dst = g_WB + (size_t)g * KTOT;
    }

    float4 v = *reinterpret_cast<const float4*>(src + col);
    __half2 h0 = __floats2half2_rn(v.x, v.y);
    __half2 h1 = __floats2half2_rn(v.z, v.w);
    uint2 u;
    u.x = *reinterpret_cast<uint32_t*>(&h0);
    u.y = *reinterpret_cast<uint32_t*>(&h1);
    *reinterpret_cast<uint2*>(dst + col) = u;
}

__global__ void shim_kernel(void) {}
__global__ void shim_kernel2(void) {}

// ---------------- fp16 GEMM (f16 accumulate, fp32 spill every K=32) + fused LSTM ----------------
__global__ __launch_bounds__(256, 1) void gemm_lstm(
    const float* __restrict__ old_state,
    const float* __restrict__ bi, const float* __restrict__ bf,
    const float* __restrict__ bo, const float* __restrict__ bs,
    float* __restrict__ out)
{
    extern __shared__ __align__(16) char smem[];
    const uint32_t smem_u = (uint32_t)__cvta_generic_to_shared(smem);

    const int tid  = threadIdx.x;
    const int lane = tid & 31;
    const int warp = tid >> 5;
    const int wm   = (warp & 1) * 64;
    const int wn   = (warp >> 1) * 64;
    const int m0   = blockIdx.y * BM;
    const int n_tile = blockIdx.x;
    const int h0   = n_tile * 64;

    const __half* gA = g_Z  + (size_t)m0 * KTOT;
    const __half* gB = g_WB + (size_t)(n_tile * BN) * KTOT;

    float* bias_sm = reinterpret_cast<float*>(smem + BIAS_BYTE_OFF);
    {
        int hl = tid >> 2, gate = tid & 3;
        const float* b = (gate == 0) ? bi : (gate == 1) ? bf : (gate == 2) ? bo : bs;
        bias_sm[tid] = b[h0 + hl];
    }

    const int lr = tid >> 3;
    const int lcb = (tid & 7) << 4;

    const uint32_t aOff = (uint32_t)((wm + (lane & 7) + ((lane >> 3) & 1) * 8) * ROWB
                                     + (lane >> 4) * 16);
    const uint32_t bOff = (uint32_t)(A_BYTES
                                     + (wn + (lane & 7) + ((lane >> 4) & 1) * 8) * ROWB
                                     + ((lane >> 3) & 1) * 16);

    float acc[4][8][4];
#pragma unroll
    for (int t = 0; t < 4; t++)
#pragma unroll
        for (int u = 0; u < 8; u++)
#pragma unroll
            for (int v = 0; v < 4; v++) acc[t][u][v] = 0.f;

    auto load_stage = [&](int kt) {
        char* As = smem + (kt % NST) * STAGE_BYTES;
        char* Bs = As + A_BYTES;
        const int k0 = kt * BK;
#pragma unroll
        for (int i = 0; i < 4; i++) {
            int r = lr + i * 32;
            cp16(As + r * ROWB + lcb, (const char*)(gA + (size_t)r * KTOT + k0) + lcb);
        }
#pragma unroll
        for (int i = 0; i < 8; i++) {
            int r = lr + i * 32;
            cp16(Bs + r * ROWB + lcb, (const char*)(gB + (size_t)r * KTOT + k0) + lcb);
        }
    };

#pragma unroll
    for (int s = 0; s < NST - 1; s++) {
        load_stage(s);
        asm volatile("cp.async.commit_group;");
    }

    uint32_t afr[2][4][4], bfr[2][4][4];

    for (int kt = 0; kt < KTILES; kt++) {
        asm volatile("cp.async.wait_group %0;" :: "n"(NST - 2));
        __syncthreads();

        const uint32_t stage = smem_u + (uint32_t)((kt % NST) * STAGE_BYTES);
        const uint32_t aBase = stage + aOff;
        const uint32_t bBase = stage + bOff;

        if (kt + NST - 1 < KTILES) load_stage(kt + NST - 1);
        asm volatile("cp.async.commit_group;");

#pragma unroll
        for (int kp = 0; kp < 2; kp++) {          // pairs of k16 -> f16 chain of K=32
            // load fragments for ks = 2kp, 2kp+1
#pragma unroll
            for (int s = 0; s < 2; s++) {
#pragma unroll
                for (int t = 0; t < 4; t++)
                    ldsm4(aBase + (2 * kp + s) * 32 + t * (16 * ROWB), afr[s][t]);
#pragma unroll
                for (int j = 0; j < 4; j++)
                    ldsm4(bBase + (2 * kp + s) * 32 + j * (16 * ROWB), bfr[s][j]);
            }
#pragma unroll
            for (int t = 0; t < 4; t++)
#pragma unroll
                for (int u = 0; u < 8; u++) {
                    const int j = u >> 1;
                    const uint32_t b00 = (u & 1) ? bfr[0][j][2] : bfr[0][j][0];
                    const uint32_t b01 = (u & 1) ? bfr[0][j][3] : bfr[0][j][1];
                    const uint32_t b10 = (u & 1) ? bfr[1][j][2] : bfr[1][j][0];
                    const uint32_t b11 = (u & 1) ? bfr[1][j][3] : bfr[1][j][1];
                    uint32_t d0, d1;
                    asm volatile(
                        "mma.sync.aligned.m16n8k16.row.col.f16.f16.f16.f16 "
                        "{%0,%1},{%2,%3,%4,%5},{%6,%7},{%8,%8};"
                        : "=r"(d0), "=r"(d1)
                        : "r"(afr[0][t][0]), "r"(afr[0][t][1]),
                          "r"(afr[0][t][2]), "r"(afr[0][t][3]),
                          "r"(b00), "r"(b01), "r"(0u));
                    asm volatile(
                        "mma.sync.aligned.m16n8k16.row.col.f16.f16.f16.f16 "
                        "{%0,%1},{%2,%3,%4,%5},{%6,%7},{%0,%1};"
                        : "+r"(d0), "+r"(d1)
                        : "r"(afr[1][t][0]), "r"(afr[1][t][1]),
                          "r"(afr[1][t][2]), "r"(afr[1][t][3]),
                          "r"(b10), "r"(b11));
                    float2 f0 = __half22float2(*reinterpret_cast<__half2*>(&d0));
                    float2 f1 = __half22float2(*reinterpret_cast<__half2*>(&d1));
                    acc[t][u][0] += f0.x;
                    acc[t][u][1] += f0.y;
                    acc[t][u][2] += f1.x;
                    acc[t][u][3] += f1.y;
                }
        }
    }

    // ---- fused LSTM gate epilogue ----
    const int hadj = (lane & 3) >> 1;
    const int row_sel = (lane & 1) << 3;
#pragma unroll
    for (int t = 0; t < 4; t++) {
        int r_out = m0 + wm + t * 16 + (lane >> 2) + row_sel;
        const float* oldr = old_state + (size_t)r_out * HDIM + h0;
        float*       outr = out       + (size_t)r_out * HDIM + h0;
#pragma unroll
        for (int u = 0; u < 8; u++) {
            float v0 = acc[t][u][0], v1 = acc[t][u][1];
            float v2 = acc[t][u][2], v3 = acc[t][u][3];
            float t0 = (lane & 1) ? v0 : v2;
            float t1 = (lane & 1) ? v1 : v3;
            float e0 = __shfl_xor_sync(0xffffffffu, t0, 1);
            float e1 = __shfl_xor_sync(0xffffffffu, t1, 1);
            float gi, gf, go, gs;
            if (lane & 1) { gi = e0; gf = e1; go = v2; gs = v3; }
            else          { gi = v0; gf = v1; go = e0; gs = e1; }
            int hl = ((wn + u * 8) >> 2) + hadj;
            gi += bias_sm[hl * 4 + 0];
            gf += bias_sm[hl * 4 + 1];
            go += bias_sm[hl * 4 + 2];
            gs += bias_sm[hl * 4 + 3];
            float c  = __ldg(oldr + hl);
            float ns = sigm(gf) * c + sigm(gi) * tanhf(gs);
            outr[hl] = sigm(go) * tanhf(ns);
        }
    }
}

extern "C" void kernel_launch(void* const* d_in, const int* in_sizes, int n_in,
                              void* d_out, int out_size)
{
    const float* x  = (const float*)d_in[0];
    const float* pt = (const float*)d_in[1];
    const float* pl = (const float*)d_in[2];
    const float* os = (const float*)d_in[3];
    const float* Wi = (const float*)d_in[4];
    const float* bi = (const float*)d_in[5];
    const float* Wf = (const float*)d_in[6];
    const float* bf = (const float*)d_in[7];
    const float* Wo = (const float*)d_in[8];
    const float* bo = (const float*)d_in[9];
    const float* Ws = (const float*)d_in[10];
    const float* bs = (const float*)d_in[11];
    float* out = (float*)d_out;

    cudaFuncSetAttribute(gemm_lstm, cudaFuncAttributeMaxDynamicSharedMemorySize, SMEM_BYTES);

    conv_all<<<dim3(5, MTOT + NTOT), 256>>>(x, pt, pl, Wi, Wf, Wo, Ws);
    shim_kernel<<<1, 32>>>();
    shim_kernel2<<<1, 32>>>();
    gemm_lstm<<<dim3(NTOT / BN, MTOT / BM), 256, SMEM_BYTES>>>(os, bi, bf, bo, bs, out);
}

// round 12
// speedup vs baseline: 1.3402x; 1.3402x over previous
#include <cuda_runtime.h>
#include <cuda_fp16.h>
#include <cstdint>
#include <cstddef>

#define MTOT 2048
#define NTOT 4096
#define KTOT 4352
#define HDIM 1024
#define XDIM 2304

#define BM 128
#define BN 256
#define BK 128                                  // halves per K-tile
#define ROWB 272                                // 256B data + 16B pad
#define A_BYTES (BM * ROWB)                     // 34816
#define B_BYTES (BN * ROWB)                     // 69632
#define STAGE_BYTES (A_BYTES + B_BYTES)         // 104448
#define BIAS_BYTE_OFF (2 * STAGE_BYTES)         // 208896
#define SMEM_BYTES (BIAS_BYTE_OFF + 1024)       // 209920
#define KTILES (KTOT / BK)                      // 34

__device__ __half g_Z[(size_t)MTOT * KTOT];
__device__ __half g_WB[(size_t)NTOT * KTOT];

__device__ __forceinline__ void cp16(void* sdst, const void* gsrc) {
    uint32_t s = (uint32_t)__cvta_generic_to_shared(sdst);
    asm volatile("cp.async.cg.shared.global [%0], [%1], 16;" :: "r"(s), "l"(gsrc));
}

__device__ __forceinline__ void ldsm4(uint32_t addr, uint32_t* r) {
    asm volatile("ldmatrix.sync.aligned.m8n8.x4.shared.b16 {%0,%1,%2,%3}, [%4];"
                 : "=r"(r[0]), "=r"(r[1]), "=r"(r[2]), "=r"(r[3]) : "r"(addr));
}

__device__ __forceinline__ float sigm(float v) { return 1.0f / (1.0f + __expf(-v)); }

// ---------------- merged grid-stride convert kernel ----------------
// dst rows: y<MTOT -> g_Z row y (concat x|pt|pl); else gate-interleaved W row.
#define C4_PER_ROW (KTOT / 4)                   // 1088
#define CONV_TOTAL ((MTOT + NTOT) * C4_PER_ROW)

__global__ __launch_bounds__(256) void conv_all(
    const float* __restrict__ x, const float* __restrict__ pt, const float* __restrict__ pl,
    const float* __restrict__ Wi, const float* __restrict__ Wf,
    const float* __restrict__ Wo, const float* __restrict__ Ws)
{
    for (int idx = blockIdx.x * blockDim.x + threadIdx.x; idx < CONV_TOTAL;
         idx += gridDim.x * blockDim.x) {
        int y = idx / C4_PER_ROW;
        int c4 = idx - y * C4_PER_ROW;
        int col = c4 * 4;

        const float* src;
        __half* dst;
        if (y < MTOT) {
            int cc;
            if (col < XDIM)             { src = x  + (size_t)y * XDIM; cc = col; }
            else if (col < XDIM + HDIM) { src = pt + (size_t)y * HDIM; cc = col - XDIM; }
            else                        { src = pl + (size_t)y * HDIM; cc = col - XDIM - HDIM; }
            src += cc - col;
            dst = g_Z + (size_t)y * KTOT;
        } else {
            int g = y - MTOT;
            int n_tile = g >> 8, r = g & 255;
            int h = n_tile * 64 + (r >> 2);
            int gate = r & 3;
            const float* W = (gate == 0) ? Wi : (gate == 1) ? Wf : (gate == 2) ? Wo : Ws;
            src = W + (size_t)h * KTOT;
            dst = g_WB + (size_t)g * KTOT;
        }

        float4 v = *reinterpret_cast<const float4*>(src + col);
        __half2 h0 = __floats2half2_rn(v.x, v.y);
        __half2 h1 = __floats2half2_rn(v.z, v.w);
        uint2 u;
        u.x = *reinterpret_cast<uint32_t*>(&h0);
        u.y = *reinterpret_cast<uint32_t*>(&h1);
        *reinterpret_cast<uint2*>(dst + col) = u;
    }
}

// ---------------- fp16 GEMM + fused LSTM: 128x256 CTA, 64x64 warp tiles, BK=128 ----------------
__global__ __launch_bounds__(256, 1) void gemm_lstm(
    const float* __restrict__ old_state,
    const float* __restrict__ bi, const float* __restrict__ bf,
    const float* __restrict__ bo, const float* __restrict__ bs,
    float* __restrict__ out)
{
    extern __shared__ __align__(16) char smem[];
    const uint32_t smem_u = (uint32_t)__cvta_generic_to_shared(smem);

    const int tid  = threadIdx.x;
    const int lane = tid & 31;
    const int warp = tid >> 5;
    const int wm   = (warp & 1) * 64;
    const int wn   = (warp >> 1) * 64;
    const int m0   = blockIdx.y * BM;
    const int n_tile = blockIdx.x;
    const int h0   = n_tile * 64;

    const __half* gA = g_Z  + (size_t)m0 * KTOT;
    const __half* gB = g_WB + (size_t)(n_tile * BN) * KTOT;

    float* bias_sm = reinterpret_cast<float*>(smem + BIAS_BYTE_OFF);   // [64][4]
    {
        int hl = tid >> 2, gate = tid & 3;
        const float* b = (gate == 0) ? bi : (gate == 1) ? bf : (gate == 2) ? bo : bs;
        bias_sm[tid] = b[h0 + hl];
    }

    // loader: rows of 256B = 16 chunks; 256 threads = 16 rows/iter
    const int lr = tid >> 4;                 // 0..15
    const int lcb = (tid & 15) << 4;         // 0..240

    const uint32_t aOff = (uint32_t)((wm + (lane & 7) + ((lane >> 3) & 1) * 8) * ROWB
                                     + (lane >> 4) * 16);
    const uint32_t bOff = (uint32_t)(A_BYTES
                                     + (wn + (lane & 7) + ((lane >> 4) & 1) * 8) * ROWB
                                     + ((lane >> 3) & 1) * 16);

    float acc[4][8][4];
#pragma unroll
    for (int t = 0; t < 4; t++)
#pragma unroll
        for (int u = 0; u < 8; u++)
#pragma unroll
            for (int v = 0; v < 4; v++) acc[t][u][v] = 0.f;

    auto load_stage = [&](int kt) {
        char* As = smem + (kt & 1) * STAGE_BYTES;
        char* Bs = As + A_BYTES;
        const int k0 = kt * BK;
#pragma unroll
        for (int i = 0; i < 8; i++) {
            int r = lr + i * 16;
            cp16(As + r * ROWB + lcb, (const char*)(gA + (size_t)r * KTOT + k0) + lcb);
        }
#pragma unroll
        for (int i = 0; i < 16; i++) {
            int r = lr + i * 16;
            cp16(Bs + r * ROWB + lcb, (const char*)(gB + (size_t)r * KTOT + k0) + lcb);
        }
    };

    load_stage(0);
    asm volatile("cp.async.commit_group;");

    uint32_t afr[2][4][4], bfr[2][4][4];

    for (int kt = 0; kt < KTILES; kt++) {
        asm volatile("cp.async.wait_group 0;");
        __syncthreads();

        if (kt + 1 < KTILES) {
            load_stage(kt + 1);
            asm volatile("cp.async.commit_group;");
        }

        const uint32_t stage = smem_u + (uint32_t)((kt & 1) * STAGE_BYTES);
        const uint32_t aBase = stage + aOff;
        const uint32_t bBase = stage + bOff;

        // prefetch ks=0 fragments
#pragma unroll
        for (int t = 0; t < 4; t++) ldsm4(aBase + t * (16 * ROWB), afr[0][t]);
#pragma unroll
        for (int j = 0; j < 4; j++) ldsm4(bBase + j * (16 * ROWB), bfr[0][j]);

#pragma unroll
        for (int ks = 0; ks < 8; ks++) {     // each ks = k16 (32B)
            const int cur = ks & 1, nxt = cur ^ 1;
            if (ks < 7) {
#pragma unroll
                for (int t = 0; t < 4; t++)
                    ldsm4(aBase + (ks + 1) * 32 + t * (16 * ROWB), afr[nxt][t]);
#pragma unroll
                for (int j = 0; j < 4; j++)
                    ldsm4(bBase + (ks + 1) * 32 + j * (16 * ROWB), bfr[nxt][j]);
            }
#pragma unroll
            for (int t = 0; t < 4; t++)
#pragma unroll
                for (int u = 0; u < 8; u++) {
                    const int j = u >> 1;
                    const uint32_t b0 = (u & 1) ? bfr[cur][j][2] : bfr[cur][j][0];
                    const uint32_t b1 = (u & 1) ? bfr[cur][j][3] : bfr[cur][j][1];
                    asm volatile(
                        "mma.sync.aligned.m16n8k16.row.col.f32.f16.f16.f32 "
                        "{%0,%1,%2,%3},{%4,%5,%6,%7},{%8,%9},{%0,%1,%2,%3};"
                        : "+f"(acc[t][u][0]), "+f"(acc[t][u][1]),
                          "+f"(acc[t][u][2]), "+f"(acc[t][u][3])
                        : "r"(afr[cur][t][0]), "r"(afr[cur][t][1]),
                          "r"(afr[cur][t][2]), "r"(afr[cur][t][3]),
                          "r"(b0), "r"(b1));
                }
        }
    }

    // ---- fused LSTM gate epilogue ----
    const int hadj = (lane & 3) >> 1;
    const int row_sel = (lane & 1) << 3;
#pragma unroll
    for (int t = 0; t < 4; t++) {
        int r_out = m0 + wm + t * 16 + (lane >> 2) + row_sel;
        const float* oldr = old_state + (size_t)r_out * HDIM + h0;
        float*       outr = out       + (size_t)r_out * HDIM + h0;
#pragma unroll
        for (int u = 0; u < 8; u++) {
            float v0 = acc[t][u][0], v1 = acc[t][u][1];
            float v2 = acc[t][u][2], v3 = acc[t][u][3];
            float t0 = (lane & 1) ? v0 : v2;
            float t1 = (lane & 1) ? v1 : v3;
            float e0 = __shfl_xor_sync(0xffffffffu, t0, 1);
            float e1 = __shfl_xor_sync(0xffffffffu, t1, 1);
            float gi, gf, go, gs;
            if (lane & 1) { gi = e0; gf = e1; go = v2; gs = v3; }
            else          { gi = v0; gf = v1; go = e0; gs = e1; }
            int hl = ((wn + u * 8) >> 2) + hadj;
            gi += bias_sm[hl * 4 + 0];
            gf += bias_sm[hl * 4 + 1];
            go += bias_sm[hl * 4 + 2];
            gs += bias_sm[hl * 4 + 3];
            float c  = __ldg(oldr + hl);
            float ns = sigm(gf) * c + sigm(gi) * tanhf(gs);
            outr[hl] = sigm(go) * tanhf(ns);
        }
    }
}

extern "C" void kernel_launch(void* const* d_in, const int* in_sizes, int n_in,
                              void* d_out, int out_size)
{
    const float* x  = (const float*)d_in[0];
    const float* pt = (const float*)d_in[1];
    const float* pl = (const float*)d_in[2];
    const float* os = (const float*)d_in[3];
    const float* Wi = (const float*)d_in[4];
    const float* bi = (const float*)d_in[5];
    const float* Wf = (const float*)d_in[6];
    const float* bf = (const float*)d_in[7];
    const float* Wo = (const float*)d_in[8];
    const float* bo = (const float*)d_in[9];
    const float* Ws = (const float*)d_in[10];
    const float* bs = (const float*)d_in[11];
    float* out = (float*)d_out;

    cudaFuncSetAttribute(gemm_lstm, cudaFuncAttributeMaxDynamicSharedMemorySize, SMEM_BYTES);

    conv_all<<<1184, 256>>>(x, pt, pl, Wi, Wf, Wo, Ws);
    gemm_lstm<<<dim3(NTOT / BN, MTOT / BM), 256, SMEM_BYTES>>>(os, bi, bf, bo, bs, out);
}